// round 11
// baseline (speedup 1.0000x reference)
#include <cuda_runtime.h>
#include <cstdint>

// ---------------- Problem constants ----------------
#define NROWS 16384
#define DIN   4096
#define DOUT  4096

// ---------------- Scratch (static __device__, allocation-free) ----------------
__device__ int8_t g_Aq[(size_t)NROWS * DIN];   // quantized activations, [M,K] row-major int8
__device__ int8_t g_Bq[(size_t)DOUT * DIN];    // quantized weights transposed, [N,K] row-major int8
__device__ unsigned g_max[2];                  // absmax bits of inputs / kernel

// ---------------- Helpers ----------------
__device__ __forceinline__ uint32_t smem_to_u32(const void* p) {
    uint32_t a;
    asm("{ .reg .u64 t; cvta.to.shared.u64 t, %1; cvt.u32.u64 %0, t; }" : "=r"(a) : "l"(p));
    return a;
}

#define CP_ASYNC16(dst, src) \
    asm volatile("cp.async.cg.shared.global [%0], [%1], 16;" :: "r"(dst), "l"(src) : "memory")
#define CP_COMMIT() asm volatile("cp.async.commit_group;" ::: "memory")
#define CP_WAIT(n)  asm volatile("cp.async.wait_group %0;" :: "n"(n) : "memory")

__device__ __forceinline__ void ldsm_x4(uint32_t* r, uint32_t addr) {
    asm volatile("ldmatrix.sync.aligned.m8n8.x4.shared.b16 {%0,%1,%2,%3}, [%4];"
                 : "=r"(r[0]), "=r"(r[1]), "=r"(r[2]), "=r"(r[3]) : "r"(addr));
}
// s8 IMMA: D(s32) += A(s8 16x32) * B(s8 32x8). Base PTX (sm_80+), exact integer math.
__device__ __forceinline__ void mma16832s8(int* c, const uint32_t* a, const uint32_t* b) {
    asm volatile(
        "mma.sync.aligned.m16n8k32.row.col.s32.s8.s8.s32 "
        "{%0,%1,%2,%3}, {%4,%5,%6,%7}, {%8,%9}, {%0,%1,%2,%3};"
        : "+r"(c[0]), "+r"(c[1]), "+r"(c[2]), "+r"(c[3])
        : "r"(a[0]), "r"(a[1]), "r"(a[2]), "r"(a[3]), "r"(b[0]), "r"(b[1]));
}

// ---------------- Kernel 0: zero the absmax accumulators ----------------
__global__ void init_kernel() {
    g_max[0] = 0u;
    g_max[1] = 0u;
}

// ---------------- Kernel 1: absmax reduction (float4 grid-stride) ----------------
__global__ void absmax_kernel(const float4* __restrict__ x, int n4, int which) {
    float m = 0.f;
    for (int i = blockIdx.x * blockDim.x + threadIdx.x; i < n4; i += gridDim.x * blockDim.x) {
        float4 v = x[i];
        m = fmaxf(m, fmaxf(fmaxf(fabsf(v.x), fabsf(v.y)), fmaxf(fabsf(v.z), fabsf(v.w))));
    }
    #pragma unroll
    for (int o = 16; o; o >>= 1) m = fmaxf(m, __shfl_xor_sync(0xFFFFFFFFu, m, o));
    __shared__ float sm[8];
    int wid = threadIdx.x >> 5, lid = threadIdx.x & 31;
    if (lid == 0) sm[wid] = m;
    __syncthreads();
    if (threadIdx.x < 32) {
        m = (threadIdx.x < (blockDim.x >> 5)) ? sm[threadIdx.x] : 0.f;
        #pragma unroll
        for (int o = 4; o; o >>= 1) m = fmaxf(m, __shfl_xor_sync(0xFFFFFFFFu, m, o));
        if (threadIdx.x == 0) atomicMax(&g_max[which], __float_as_uint(m));
    }
}

// ---------------- Kernel 2: quantize activations -> int8 ----------------
__global__ void quantA_kernel(const float4* __restrict__ x, int n4) {
    const float inv = 127.f / (__uint_as_float(g_max[0]) + 1e-8f);
    uint32_t* out = (uint32_t*)g_Aq;
    for (int i = blockIdx.x * blockDim.x + threadIdx.x; i < n4; i += gridDim.x * blockDim.x) {
        float4 v = x[i];
        int a = __float2int_rn(v.x * inv);
        int b = __float2int_rn(v.y * inv);
        int c = __float2int_rn(v.z * inv);
        int d = __float2int_rn(v.w * inv);
        out[i] = (uint32_t)(a & 0xFF) | ((uint32_t)(b & 0xFF) << 8) |
                 ((uint32_t)(c & 0xFF) << 16) | ((uint32_t)(d & 0xFF) << 24);
    }
}

// ---------------- Kernel 3: transpose + quantize weights -> [N,K] int8 ----------------
__global__ void quantB_kernel(const float* __restrict__ w) {
    __shared__ float tile[32][33];
    int n0 = blockIdx.x * 32;
    int k0 = blockIdx.y * 32;
    int tx = threadIdx.x, ty = threadIdx.y;   // block (32, 8)
    #pragma unroll
    for (int j = 0; j < 32; j += 8)
        tile[ty + j][tx] = w[(size_t)(k0 + ty + j) * DOUT + n0 + tx];
    __syncthreads();
    const float inv = 127.f / (__uint_as_float(g_max[1]) + 1e-8f);
    #pragma unroll
    for (int j = 0; j < 32; j += 8) {
        int q = __float2int_rn(tile[tx][ty + j] * inv);  // w[k0+tx][n0+ty+j]
        g_Bq[(size_t)(n0 + ty + j) * DIN + (k0 + tx)] = (int8_t)q;
    }
}

// ---------------- Kernel 4: s8 IMMA GEMM, 128x256 output tile per CTA ----------------
// 8 warps of 64x64, mma.sync m16n8k32 s8, cp.async double-buffered BK=64 bytes,
// 80B-padded smem rows (conflict-free ldmatrix, same layout as the bf16 version).
static constexpr int GTHREADS = 256;
static constexpr int SMEM_BYTES = 2 * 10240 + 2 * 20480;  // 61440B

__global__ void __launch_bounds__(GTHREADS)
gemm_kernel(const float* __restrict__ bias, float* __restrict__ out) {
    extern __shared__ char smem_raw[];
    const uint32_t sb = smem_to_u32(smem_raw);
    const int tid = threadIdx.x, lid = tid & 31, wid = tid >> 5;
    const int m0 = blockIdx.y * 128, n0 = blockIdx.x * 256;
    const int wm0 = (wid & 1) * 64, wn0 = (wid >> 1) * 64;

    // smem: A buffers 128 rows x 64B (padded to 80B) = 10240B each; B 256x64B = 20480B each
    const uint32_t A0 = sb, A1 = sb + 10240, B0 = sb + 20480, B1 = sb + 40960;

    const int8_t* Ag = g_Aq + (size_t)m0 * DIN;
    const int8_t* Bg = g_Bq + (size_t)n0 * DIN;

    auto load_tiles = [&](int kc, uint32_t a_s, uint32_t b_s) {
        const int kb = kc * 64;                    // byte offset along K
        #pragma unroll
        for (int j = 0; j < 2; j++) {              // A: 128 rows x 4 x 16B = 512 ops
            int idx = tid + j * GTHREADS;
            int r = idx >> 2, c = idx & 3;
            CP_ASYNC16(a_s + r * 80 + c * 16, Ag + (size_t)r * DIN + kb + c * 16);
        }
        #pragma unroll
        for (int j = 0; j < 4; j++) {              // B: 256 rows x 4 x 16B = 1024 ops
            int idx = tid + j * GTHREADS;
            int r = idx >> 2, c = idx & 3;
            CP_ASYNC16(b_s + r * 80 + c * 16, Bg + (size_t)r * DIN + kb + c * 16);
        }
    };

    int acc[4][8][4] = {};
    const uint32_t g = lid >> 3, r8 = lid & 7;
    const int ITERS = DIN / 64;  // 64

    load_tiles(0, A0, B0);
    CP_COMMIT();

    for (int kc = 0; kc < ITERS; ++kc) {
        const uint32_t a_s = (kc & 1) ? A1 : A0;
        const uint32_t b_s = (kc & 1) ? B1 : B0;
        if (kc + 1 < ITERS) {
            load_tiles(kc + 1, (kc & 1) ? A0 : A1, (kc & 1) ? B0 : B1);
            CP_COMMIT();
            CP_WAIT(1);
        } else {
            CP_WAIT(0);
        }
        __syncthreads();

        #pragma unroll
        for (int ks = 0; ks < 2; ++ks) {           // two k=32 steps cover BK=64
            uint32_t a[4][4], b[8][2];
            // A fragments: 16x32 s8 tile == 16x16 b16-units; same ldmatrix pattern as bf16
            #pragma unroll
            for (int mi = 0; mi < 4; ++mi) {
                uint32_t row = wm0 + mi * 16 + ((g & 1u) << 3) + r8;
                uint32_t colb = ks * 32 + ((g >> 1) << 4);       // byte offset in row
                ldsm_x4(a[mi], a_s + row * 80 + colb);
            }
            // B fragments: two n8-tiles per ldmatrix.x4 (rows = n, 32 bytes of k)
            #pragma unroll
            for (int p = 0; p < 4; ++p) {
                uint32_t row = wn0 + p * 16 + ((g >> 1) << 3) + r8;
                uint32_t colb = ks * 32 + ((g & 1u) << 4);
                uint32_t t[4];
                ldsm_x4(t, b_s + row * 80 + colb);
                b[p * 2][0] = t[0]; b[p * 2][1] = t[1];
                b[p * 2 + 1][0] = t[2]; b[p * 2 + 1][1] = t[3];
            }
            #pragma unroll
            for (int mi = 0; mi < 4; ++mi)
                #pragma unroll
                for (int ni = 0; ni < 8; ++ni)
                    mma16832s8(acc[mi][ni], a[mi], b[ni]);
        }
        __syncthreads();
    }

    // Epilogue: exact s32 counts -> f32 scale + bias
    float sA = __uint_as_float(g_max[0]) + 1e-8f;
    float sB = __uint_as_float(g_max[1]) + 1e-8f;
    float fs = sA * sB * (1.f / 16129.f);   // /(127*127)

    #pragma unroll
    for (int mi = 0; mi < 4; ++mi) {
        int row = m0 + wm0 + mi * 16 + (lid >> 2);
        #pragma unroll
        for (int ni = 0; ni < 8; ++ni) {
            int col = n0 + wn0 + ni * 8 + ((lid & 3) << 1);
            float b0 = bias[col], b1 = bias[col + 1];
            float2 v0, v1;
            v0.x = (float)acc[mi][ni][0] * fs + b0;
            v0.y = (float)acc[mi][ni][1] * fs + b1;
            v1.x = (float)acc[mi][ni][2] * fs + b0;
            v1.y = (float)acc[mi][ni][3] * fs + b1;
            *(float2*)(out + (size_t)row * DOUT + col) = v0;
            *(float2*)(out + (size_t)(row + 8) * DOUT + col) = v1;
        }
    }
}

// ---------------- Launch ----------------
extern "C" void kernel_launch(void* const* d_in, const int* in_sizes, int n_in,
                              void* d_out, int out_size) {
    const float* inp  = (const float*)d_in[0];   // [16384, 4096]
    const float* ker  = (const float*)d_in[1];   // [4096, 4096]
    const float* bias = (const float*)d_in[2];   // [4096]
    float* out = (float*)d_out;

    cudaFuncSetAttribute(gemm_kernel, cudaFuncAttributeMaxDynamicSharedMemorySize, SMEM_BYTES);

    init_kernel<<<1, 1>>>();

    absmax_kernel<<<1024, 256>>>((const float4*)inp, (NROWS * DIN) / 4, 0);
    absmax_kernel<<<512, 256>>>((const float4*)ker, (DIN * DOUT) / 4, 1);

    quantA_kernel<<<2048, 256>>>((const float4*)inp, (NROWS * DIN) / 4);

    dim3 bgrid(DOUT / 32, DIN / 32);
    quantB_kernel<<<bgrid, dim3(32, 8)>>>(ker);

    dim3 ggrid(DOUT / 256, NROWS / 128);   // (16, 128); x-fastest -> A-band reuse in L2
    gemm_kernel<<<ggrid, GTHREADS, SMEM_BYTES>>>(bias, out);
}

// round 16
// speedup vs baseline: 1.5819x; 1.5819x over previous
#include <cuda_runtime.h>
#include <cuda_bf16.h>
#include <cstdint>

// ---------------- Problem constants ----------------
#define NROWS 16384
#define DIN   4096
#define DOUT  4096

// ---------------- Scratch (static __device__, allocation-free) ----------------
__device__ __nv_bfloat16 g_Aq[(size_t)NROWS * DIN];   // quantized activations, [M,K] row-major
__device__ __nv_bfloat16 g_Bq[(size_t)DOUT * DIN];    // quantized weights transposed, [N,K] row-major
__device__ unsigned g_max[2];                          // absmax bits of inputs / kernel

// ---------------- Helpers ----------------
__device__ __forceinline__ uint32_t smem_to_u32(const void* p) {
    uint32_t a;
    asm("{ .reg .u64 t; cvta.to.shared.u64 t, %1; cvt.u32.u64 %0, t; }" : "=r"(a) : "l"(p));
    return a;
}

#define CP_ASYNC16(dst, src) \
    asm volatile("cp.async.cg.shared.global [%0], [%1], 16;" :: "r"(dst), "l"(src) : "memory")
#define CP_COMMIT() asm volatile("cp.async.commit_group;" ::: "memory")
#define CP_WAIT(n)  asm volatile("cp.async.wait_group %0;" :: "n"(n) : "memory")

__device__ __forceinline__ void ldsm_x4(uint32_t* r, uint32_t addr) {
    asm volatile("ldmatrix.sync.aligned.m8n8.x4.shared.b16 {%0,%1,%2,%3}, [%4];"
                 : "=r"(r[0]), "=r"(r[1]), "=r"(r[2]), "=r"(r[3]) : "r"(addr));
}
__device__ __forceinline__ void mma16816(float* c, const uint32_t* a, const uint32_t* b) {
    asm volatile(
        "mma.sync.aligned.m16n8k16.row.col.f32.bf16.bf16.f32 "
        "{%0,%1,%2,%3}, {%4,%5,%6,%7}, {%8,%9}, {%0,%1,%2,%3};"
        : "+f"(c[0]), "+f"(c[1]), "+f"(c[2]), "+f"(c[3])
        : "r"(a[0]), "r"(a[1]), "r"(a[2]), "r"(a[3]), "r"(b[0]), "r"(b[1]));
}

// ---------------- Kernel 0: zero the absmax accumulators ----------------
__global__ void init_kernel() {
    g_max[0] = 0u;
    g_max[1] = 0u;
}

// ---------------- Kernel 1: absmax reduction (float4 grid-stride) ----------------
__global__ void absmax_kernel(const float4* __restrict__ x, int n4, int which) {
    float m = 0.f;
    for (int i = blockIdx.x * blockDim.x + threadIdx.x; i < n4; i += gridDim.x * blockDim.x) {
        float4 v = x[i];
        m = fmaxf(m, fmaxf(fmaxf(fabsf(v.x), fabsf(v.y)), fmaxf(fabsf(v.z), fabsf(v.w))));
    }
    #pragma unroll
    for (int o = 16; o; o >>= 1) m = fmaxf(m, __shfl_xor_sync(0xFFFFFFFFu, m, o));
    __shared__ float sm[8];
    int wid = threadIdx.x >> 5, lid = threadIdx.x & 31;
    if (lid == 0) sm[wid] = m;
    __syncthreads();
    if (threadIdx.x < 32) {
        m = (threadIdx.x < (blockDim.x >> 5)) ? sm[threadIdx.x] : 0.f;
        #pragma unroll
        for (int o = 4; o; o >>= 1) m = fmaxf(m, __shfl_xor_sync(0xFFFFFFFFu, m, o));
        if (threadIdx.x == 0) atomicMax(&g_max[which], __float_as_uint(m));
    }
}

// ---------------- Kernel 2: quantize activations -> integer-valued bf16 ----------------
__global__ void quantA_kernel(const float4* __restrict__ x, int n4) {
    const float inv = 127.f / (__uint_as_float(g_max[0]) + 1e-8f);
    uint2* out = (uint2*)g_Aq;
    for (int i = blockIdx.x * blockDim.x + threadIdx.x; i < n4; i += gridDim.x * blockDim.x) {
        float4 v = x[i];
        __nv_bfloat162 lo = __floats2bfloat162_rn(rintf(v.x * inv), rintf(v.y * inv));
        __nv_bfloat162 hi = __floats2bfloat162_rn(rintf(v.z * inv), rintf(v.w * inv));
        uint2 o;
        o.x = *reinterpret_cast<uint32_t*>(&lo);
        o.y = *reinterpret_cast<uint32_t*>(&hi);
        out[i] = o;
    }
}

// ---------------- Kernel 3: transpose + quantize weights -> [N,K] bf16 ----------------
__global__ void quantB_kernel(const float* __restrict__ w) {
    __shared__ float tile[32][33];
    int n0 = blockIdx.x * 32;
    int k0 = blockIdx.y * 32;
    int tx = threadIdx.x, ty = threadIdx.y;   // block (32, 8)
    #pragma unroll
    for (int j = 0; j < 32; j += 8)
        tile[ty + j][tx] = w[(size_t)(k0 + ty + j) * DOUT + n0 + tx];
    __syncthreads();
    const float inv = 127.f / (__uint_as_float(g_max[1]) + 1e-8f);
    #pragma unroll
    for (int j = 0; j < 32; j += 8) {
        float q = rintf(tile[tx][ty + j] * inv);  // w[k0+tx][n0+ty+j]
        g_Bq[(size_t)(n0 + ty + j) * DIN + (k0 + tx)] = __float2bfloat16(q);
    }
}

// ---------------- Kernel 4: bf16 HMMA GEMM, 128x256 tile, BK=64, double buffered ----------
// 8 warps of 64x64, mma.sync m16n8k16 bf16. Smem rows: 64 bf16 = 128B, padded to 144B
// (144/4 = 36 banks ≡ 4 mod 32 -> the 8 rows of one ldmatrix hit disjoint 4-bank groups).
static constexpr int GTHREADS = 256;
static constexpr int A_ST = 144;                    // bytes per A/B smem row
static constexpr int A_TILE = 128 * A_ST;           // 18432B
static constexpr int B_TILE = 256 * A_ST;           // 36864B
static constexpr int SMEM_BYTES = 2 * A_TILE + 2 * B_TILE;  // 110592B

__global__ void __launch_bounds__(GTHREADS)
gemm_kernel(const float* __restrict__ bias, float* __restrict__ out) {
    extern __shared__ char smem_raw[];
    const uint32_t sb = smem_to_u32(smem_raw);
    const int tid = threadIdx.x, lid = tid & 31, wid = tid >> 5;
    const int m0 = blockIdx.y * 128, n0 = blockIdx.x * 256;
    const int wm0 = (wid & 1) * 64, wn0 = (wid >> 1) * 64;

    const uint32_t A0 = sb, A1 = sb + A_TILE;
    const uint32_t B0 = sb + 2 * A_TILE, B1 = B0 + B_TILE;

    const __nv_bfloat16* Ag = g_Aq + (size_t)m0 * DIN;
    const __nv_bfloat16* Bg = g_Bq + (size_t)n0 * DIN;

    auto load_tiles = [&](int kc, uint32_t a_s, uint32_t b_s) {
        const int kb = kc * 64;                    // element offset along K
        #pragma unroll
        for (int j = 0; j < 4; j++) {              // A: 128 rows x 8 x 16B = 1024 ops
            int idx = tid + j * GTHREADS;
            int r = idx >> 3, c = idx & 7;
            CP_ASYNC16(a_s + r * A_ST + c * 16, Ag + (size_t)r * DIN + kb + c * 8);
        }
        #pragma unroll
        for (int j = 0; j < 8; j++) {              // B: 256 rows x 8 x 16B = 2048 ops
            int idx = tid + j * GTHREADS;
            int r = idx >> 3, c = idx & 7;
            CP_ASYNC16(b_s + r * A_ST + c * 16, Bg + (size_t)r * DIN + kb + c * 8);
        }
    };

    float acc[4][8][4] = {};
    const uint32_t g = lid >> 3, r8 = lid & 7;
    const int ITERS = DIN / 64;  // 64

    load_tiles(0, A0, B0);
    CP_COMMIT();

    for (int kc = 0; kc < ITERS; ++kc) {
        const uint32_t a_s = (kc & 1) ? A1 : A0;
        const uint32_t b_s = (kc & 1) ? B1 : B0;
        if (kc + 1 < ITERS) {
            load_tiles(kc + 1, (kc & 1) ? A0 : A1, (kc & 1) ? B0 : B1);
            CP_COMMIT();
            CP_WAIT(1);
        } else {
            CP_WAIT(0);
        }
        __syncthreads();

        #pragma unroll
        for (int ks = 0; ks < 4; ++ks) {           // four k=16 steps cover BK=64
            uint32_t a[4][4], b[8][2];
            #pragma unroll
            for (int mi = 0; mi < 4; ++mi) {
                uint32_t row = wm0 + mi * 16 + ((g & 1u) << 3) + r8;
                uint32_t colb = ks * 32 + ((g >> 1) << 4);   // byte offset within row
                ldsm_x4(a[mi], a_s + row * A_ST + colb);
            }
            #pragma unroll
            for (int p = 0; p < 4; ++p) {
                uint32_t row = wn0 + p * 16 + ((g >> 1) << 3) + r8;
                uint32_t colb = ks * 32 + ((g & 1u) << 4);
                uint32_t t[4];
                ldsm_x4(t, b_s + row * A_ST + colb);
                b[p * 2][0] = t[0]; b[p * 2][1] = t[1];
                b[p * 2 + 1][0] = t[2]; b[p * 2 + 1][1] = t[3];
            }
            #pragma unroll
            for (int mi = 0; mi < 4; ++mi)
                #pragma unroll
                for (int ni = 0; ni < 8; ++ni)
                    mma16816(acc[mi][ni], a[mi], b[ni]);
        }
        __syncthreads();
    }

    // Epilogue
    float sA = __uint_as_float(g_max[0]) + 1e-8f;
    float sB = __uint_as_float(g_max[1]) + 1e-8f;
    float fs = sA * sB * (1.f / 16129.f);

    #pragma unroll
    for (int mi = 0; mi < 4; ++mi) {
        int row = m0 + wm0 + mi * 16 + (lid >> 2);
        #pragma unroll
        for (int ni = 0; ni < 8; ++ni) {
            int col = n0 + wn0 + ni * 8 + ((lid & 3) << 1);
            float b0 = bias[col], b1 = bias[col + 1];
            float2 v0, v1;
            v0.x = acc[mi][ni][0] * fs + b0;
            v0.y = acc[mi][ni][1] * fs + b1;
            v1.x = acc[mi][ni][2] * fs + b0;
            v1.y = acc[mi][ni][3] * fs + b1;
            *(float2*)(out + (size_t)row * DOUT + col) = v0;
            *(float2*)(out + (size_t)(row + 8) * DOUT + col) = v1;
        }
    }
}

// ---------------- Launch ----------------
extern "C" void kernel_launch(void* const* d_in, const int* in_sizes, int n_in,
                              void* d_out, int out_size) {
    const float* inp  = (const float*)d_in[0];   // [16384, 4096]
    const float* ker  = (const float*)d_in[1];   // [4096, 4096]
    const float* bias = (const float*)d_in[2];   // [4096]
    float* out = (float*)d_out;

    cudaFuncSetAttribute(gemm_kernel, cudaFuncAttributeMaxDynamicSharedMemorySize, SMEM_BYTES);

    init_kernel<<<1, 1>>>();

    absmax_kernel<<<1024, 256>>>((const float4*)inp, (NROWS * DIN) / 4, 0);
    absmax_kernel<<<512, 256>>>((const float4*)ker, (DIN * DOUT) / 4, 1);

    quantA_kernel<<<2048, 256>>>((const float4*)inp, (NROWS * DIN) / 4);

    dim3 bgrid(DOUT / 32, DIN / 32);
    quantB_kernel<<<bgrid, dim3(32, 8)>>>(ker);

    dim3 ggrid(DOUT / 256, NROWS / 128);   // (16, 128); x-fastest -> A-band reuse in L2
    gemm_kernel<<<ggrid, GTHREADS, SMEM_BYTES>>>(bias, out);
}

// round 17
// speedup vs baseline: 2.3588x; 1.4912x over previous
#include <cuda_runtime.h>
#include <cuda_bf16.h>
#include <cstdint>

// ---------------- Problem constants ----------------
#define NROWS 16384
#define DIN   4096
#define DOUT  4096

// ---------------- Scratch (static __device__, allocation-free) ----------------
__device__ __nv_bfloat16 g_Aq[(size_t)NROWS * DIN];   // quantized activations, [M,K] row-major
__device__ __nv_bfloat16 g_Bq[(size_t)DOUT * DIN];    // quantized weights transposed, [N,K] row-major
__device__ unsigned g_max[2];                          // absmax bits of inputs / kernel

// ---------------- Helpers ----------------
__device__ __forceinline__ uint32_t smem_to_u32(const void* p) {
    uint32_t a;
    asm("{ .reg .u64 t; cvta.to.shared.u64 t, %1; cvt.u32.u64 %0, t; }" : "=r"(a) : "l"(p));
    return a;
}

#define CP_ASYNC16(dst, src) \
    asm volatile("cp.async.cg.shared.global [%0], [%1], 16;" :: "r"(dst), "l"(src) : "memory")
#define CP_COMMIT() asm volatile("cp.async.commit_group;" ::: "memory")
#define CP_WAIT(n)  asm volatile("cp.async.wait_group %0;" :: "n"(n) : "memory")

__device__ __forceinline__ void ldsm_x4(uint32_t* r, uint32_t addr) {
    asm volatile("ldmatrix.sync.aligned.m8n8.x4.shared.b16 {%0,%1,%2,%3}, [%4];"
                 : "=r"(r[0]), "=r"(r[1]), "=r"(r[2]), "=r"(r[3]) : "r"(addr));
}
__device__ __forceinline__ void mma16816(float* c, const uint32_t* a, const uint32_t* b) {
    asm volatile(
        "mma.sync.aligned.m16n8k16.row.col.f32.bf16.bf16.f32 "
        "{%0,%1,%2,%3}, {%4,%5,%6,%7}, {%8,%9}, {%0,%1,%2,%3};"
        : "+f"(c[0]), "+f"(c[1]), "+f"(c[2]), "+f"(c[3])
        : "r"(a[0]), "r"(a[1]), "r"(a[2]), "r"(a[3]), "r"(b[0]), "r"(b[1]));
}

// ---------------- Kernel 0: zero the absmax accumulators ----------------
__global__ void init_kernel() {
    g_max[0] = 0u;
    g_max[1] = 0u;
}

// ---------------- Kernel 1: absmax reduction (float4 grid-stride) ----------------
__global__ void absmax_kernel(const float4* __restrict__ x, int n4, int which) {
    float m = 0.f;
    for (int i = blockIdx.x * blockDim.x + threadIdx.x; i < n4; i += gridDim.x * blockDim.x) {
        float4 v = x[i];
        m = fmaxf(m, fmaxf(fmaxf(fabsf(v.x), fabsf(v.y)), fmaxf(fabsf(v.z), fabsf(v.w))));
    }
    #pragma unroll
    for (int o = 16; o; o >>= 1) m = fmaxf(m, __shfl_xor_sync(0xFFFFFFFFu, m, o));
    __shared__ float sm[8];
    int wid = threadIdx.x >> 5, lid = threadIdx.x & 31;
    if (lid == 0) sm[wid] = m;
    __syncthreads();
    if (threadIdx.x < 32) {
        m = (threadIdx.x < (blockDim.x >> 5)) ? sm[threadIdx.x] : 0.f;
        #pragma unroll
        for (int o = 4; o; o >>= 1) m = fmaxf(m, __shfl_xor_sync(0xFFFFFFFFu, m, o));
        if (threadIdx.x == 0) atomicMax(&g_max[which], __float_as_uint(m));
    }
}

// ---------------- Kernel 2: quantize activations -> integer-valued bf16 ----------------
__global__ void quantA_kernel(const float4* __restrict__ x, int n4) {
    const float inv = 127.f / (__uint_as_float(g_max[0]) + 1e-8f);
    uint2* out = (uint2*)g_Aq;
    for (int i = blockIdx.x * blockDim.x + threadIdx.x; i < n4; i += gridDim.x * blockDim.x) {
        float4 v = x[i];
        __nv_bfloat162 lo = __floats2bfloat162_rn(rintf(v.x * inv), rintf(v.y * inv));
        __nv_bfloat162 hi = __floats2bfloat162_rn(rintf(v.z * inv), rintf(v.w * inv));
        uint2 o;
        o.x = *reinterpret_cast<uint32_t*>(&lo);
        o.y = *reinterpret_cast<uint32_t*>(&hi);
        out[i] = o;
    }
}

// ---------------- Kernel 3: transpose + quantize weights -> [N,K] bf16 ----------------
__global__ void quantB_kernel(const float* __restrict__ w) {
    __shared__ float tile[32][33];
    int n0 = blockIdx.x * 32;
    int k0 = blockIdx.y * 32;
    int tx = threadIdx.x, ty = threadIdx.y;   // block (32, 8)
    #pragma unroll
    for (int j = 0; j < 32; j += 8)
        tile[ty + j][tx] = w[(size_t)(k0 + ty + j) * DOUT + n0 + tx];
    __syncthreads();
    const float inv = 127.f / (__uint_as_float(g_max[1]) + 1e-8f);
    #pragma unroll
    for (int j = 0; j < 32; j += 8) {
        float q = rintf(tile[tx][ty + j] * inv);  // w[k0+tx][n0+ty+j]
        g_Bq[(size_t)(n0 + ty + j) * DIN + (k0 + tx)] = __float2bfloat16(q);
    }
}

// ---------------- Kernel 4: bf16 HMMA GEMM, 128x128 tile, 4 warps, BK=32 -----------------
// Warp-level code identical to the proven 1245us kernel (80B rows, 2-step inner body).
// Smaller CTA -> 40KB smem + 128 threads => 2 CTAs/SM co-resident (overlap sync/load bubbles).
static constexpr int GTHREADS = 128;
static constexpr int T_ST = 80;                        // bytes per smem row (proven pitch)
static constexpr int TILE_B = 128 * T_ST;              // 10240B per A or B stage
static constexpr int SMEM_BYTES = 4 * TILE_B;          // 40960B

__global__ void __launch_bounds__(GTHREADS)
gemm_kernel(const float* __restrict__ bias, float* __restrict__ out) {
    extern __shared__ char smem_raw[];
    const uint32_t sb = smem_to_u32(smem_raw);
    const int tid = threadIdx.x, lid = tid & 31, wid = tid >> 5;   // 4 warps
    const int m0 = blockIdx.y * 128, n0 = blockIdx.x * 128;
    const int wm0 = (wid & 1) * 64, wn0 = (wid >> 1) * 64;         // 2x2 warp grid

    const uint32_t A0 = sb, A1 = sb + TILE_B;
    const uint32_t B0 = sb + 2 * TILE_B, B1 = sb + 3 * TILE_B;

    const __nv_bfloat16* Ag = g_Aq + (size_t)m0 * DIN;
    const __nv_bfloat16* Bg = g_Bq + (size_t)n0 * DIN;

    auto load_tiles = [&](int kc, uint32_t a_s, uint32_t b_s) {
        const int kb = kc * 32;
        #pragma unroll
        for (int j = 0; j < 4; j++) {              // A: 128 rows x 4 x 16B = 512 ops
            int idx = tid + j * GTHREADS;
            int r = idx >> 2, c = idx & 3;
            CP_ASYNC16(a_s + r * T_ST + c * 16, Ag + (size_t)r * DIN + kb + c * 8);
        }
        #pragma unroll
        for (int j = 0; j < 4; j++) {              // B: 128 rows x 4 x 16B = 512 ops
            int idx = tid + j * GTHREADS;
            int r = idx >> 2, c = idx & 3;
            CP_ASYNC16(b_s + r * T_ST + c * 16, Bg + (size_t)r * DIN + kb + c * 8);
        }
    };

    float acc[4][8][4] = {};
    const uint32_t g = lid >> 3, r8 = lid & 7;
    const int ITERS = DIN / 32;  // 128

    load_tiles(0, A0, B0);
    CP_COMMIT();

    for (int kc = 0; kc < ITERS; ++kc) {
        const uint32_t a_s = (kc & 1) ? A1 : A0;
        const uint32_t b_s = (kc & 1) ? B1 : B0;
        if (kc + 1 < ITERS) {
            load_tiles(kc + 1, (kc & 1) ? A0 : A1, (kc & 1) ? B0 : B1);
            CP_COMMIT();
            CP_WAIT(1);
        } else {
            CP_WAIT(0);
        }
        __syncthreads();

        #pragma unroll
        for (int ks = 0; ks < 2; ++ks) {
            uint32_t a[4][4], b[8][2];
            #pragma unroll
            for (int mi = 0; mi < 4; ++mi) {
                uint32_t row = wm0 + mi * 16 + ((g & 1u) << 3) + r8;
                uint32_t col = ks * 16 + ((g >> 1) << 3);
                ldsm_x4(a[mi], a_s + row * T_ST + col * 2);
            }
            #pragma unroll
            for (int p = 0; p < 4; ++p) {
                uint32_t row = wn0 + p * 16 + ((g >> 1) << 3) + r8;
                uint32_t col = ks * 16 + ((g & 1u) << 3);
                uint32_t t[4];
                ldsm_x4(t, b_s + row * T_ST + col * 2);
                b[p * 2][0] = t[0]; b[p * 2][1] = t[1];
                b[p * 2 + 1][0] = t[2]; b[p * 2 + 1][1] = t[3];
            }
            #pragma unroll
            for (int mi = 0; mi < 4; ++mi)
                #pragma unroll
                for (int ni = 0; ni < 8; ++ni)
                    mma16816(acc[mi][ni], a[mi], b[ni]);
        }
        __syncthreads();
    }

    // Epilogue
    float sA = __uint_as_float(g_max[0]) + 1e-8f;
    float sB = __uint_as_float(g_max[1]) + 1e-8f;
    float fs = sA * sB * (1.f / 16129.f);

    #pragma unroll
    for (int mi = 0; mi < 4; ++mi) {
        int row = m0 + wm0 + mi * 16 + (lid >> 2);
        #pragma unroll
        for (int ni = 0; ni < 8; ++ni) {
            int col = n0 + wn0 + ni * 8 + ((lid & 3) << 1);
            float b0 = bias[col], b1 = bias[col + 1];
            float2 v0, v1;
            v0.x = acc[mi][ni][0] * fs + b0;
            v0.y = acc[mi][ni][1] * fs + b1;
            v1.x = acc[mi][ni][2] * fs + b0;
            v1.y = acc[mi][ni][3] * fs + b1;
            *(float2*)(out + (size_t)row * DOUT + col) = v0;
            *(float2*)(out + (size_t)(row + 8) * DOUT + col) = v1;
        }
    }
}

// ---------------- Launch ----------------
extern "C" void kernel_launch(void* const* d_in, const int* in_sizes, int n_in,
                              void* d_out, int out_size) {
    const float* inp  = (const float*)d_in[0];   // [16384, 4096]
    const float* ker  = (const float*)d_in[1];   // [4096, 4096]
    const float* bias = (const float*)d_in[2];   // [4096]
    float* out = (float*)d_out;

    cudaFuncSetAttribute(gemm_kernel, cudaFuncAttributeMaxDynamicSharedMemorySize, SMEM_BYTES);

    init_kernel<<<1, 1>>>();

    absmax_kernel<<<1024, 256>>>((const float4*)inp, (NROWS * DIN) / 4, 0);
    absmax_kernel<<<512, 256>>>((const float4*)ker, (DIN * DOUT) / 4, 1);

    quantA_kernel<<<4096, 256>>>((const float4*)inp, (NROWS * DIN) / 4);

    dim3 bgrid(DOUT / 32, DIN / 32);
    quantB_kernel<<<bgrid, dim3(32, 8)>>>(ker);

    dim3 ggrid(DOUT / 128, NROWS / 128);   // (32, 128); x-fastest -> A-band reuse in L2
    gemm_kernel<<<ggrid, GTHREADS, SMEM_BYTES>>>(bias, out);
}